// round 1
// baseline (speedup 1.0000x reference)
#include <cuda_runtime.h>
#include <cstdint>
#include <cstddef>

// Problem constants (from reference setup_inputs)
#define BB    16
#define TT    8192
#define DD    192
#define KC    512
#define SPAN  8
#define NSEG  16384     // BB*TT/SPAN
#define NTOK  131072    // BB*TT

// Output packing: q_out [B,T,D] f32, total_loss [1], idx_out [B,T] (as f32), boundaries [B,T]
#define OFF_LOSS 25165824
#define OFF_IDX  25165825
#define OFF_BND  25296897

// Scratch (device globals — no allocations allowed)
__device__ float g_pooled[NSEG * DD];   // 12.6 MB
__device__ float g_pnorm[NSEG];
__device__ int   g_idx[NSEG];
__device__ float g_cbnorm[KC];
__device__ float g_elatent;
__device__ int   g_bcount;

// ---------------------------------------------------------------------------
// K0: reset accumulators + codebook squared norms (per graph replay)
// ---------------------------------------------------------------------------
__global__ void k_init(const float* __restrict__ cb) {
    int c = blockIdx.x * 256 + threadIdx.x;
    if (c == 0) { g_elatent = 0.f; g_bcount = 0; }
    if (c < KC) {
        const float4* r = (const float4*)(cb + (size_t)c * DD);
        float s = 0.f;
#pragma unroll
        for (int k = 0; k < DD / 4; k++) {
            float4 v = r[k];
            s += v.x * v.x + v.y * v.y + v.z * v.z + v.w * v.w;
        }
        g_cbnorm[c] = s;
    }
}

// ---------------------------------------------------------------------------
// K1: fused segment pooling + pooled-norm + boundary predictor (one pass over x)
// One block per segment (8 tokens x 192 dims), 192 threads (thread = dim).
// ---------------------------------------------------------------------------
__global__ void __launch_bounds__(192) k_pool(const float* __restrict__ x,
                                              const float* __restrict__ w,
                                              const float* __restrict__ bbias,
                                              float* __restrict__ out_bnd) {
    int seg = blockIdx.x;
    int d   = threadIdx.x;
    // tokens of segment are contiguous: global token = seg*SPAN + j
    const float* xp = x + (size_t)seg * (SPAN * DD) + d;
    float wd  = w[d];
    float part[SPAN];
    float sum = 0.f;
#pragma unroll
    for (int j = 0; j < SPAN; j++) {
        float v = xp[(size_t)j * DD];
        sum += v;
        part[j] = v * wd;
    }
    float p = sum * (1.0f / SPAN);
    g_pooled[(size_t)seg * DD + d] = p;
    float pn = p * p;

    // warp reduce 8 boundary partials + pooled norm partial
#pragma unroll
    for (int off = 16; off; off >>= 1) {
#pragma unroll
        for (int j = 0; j < SPAN; j++)
            part[j] += __shfl_down_sync(0xffffffffu, part[j], off);
        pn += __shfl_down_sync(0xffffffffu, pn, off);
    }
    __shared__ float sh[6][9];
    int wp = d >> 5, ln = d & 31;
    if (ln == 0) {
#pragma unroll
        for (int j = 0; j < SPAN; j++) sh[wp][j] = part[j];
        sh[wp][8] = pn;
    }
    __syncthreads();
    if (d < SPAN) {
        float z = bbias[0];
#pragma unroll
        for (int k = 0; k < 6; k++) z += sh[k][d];
        bool hi = z > 0.f;                     // sigmoid(z) > 0.5  <=>  z > 0
        out_bnd[seg * SPAN + d] = hi ? 1.f : 0.f;
        unsigned bal = __ballot_sync(0x000000ffu, hi);
        if (d == 0) atomicAdd(&g_bcount, __popc(bal & 0xffu));
    } else if (d == SPAN) {
        float pn2 = 0.f;
#pragma unroll
        for (int k = 0; k < 6; k++) pn2 += sh[k][8];
        g_pnorm[seg] = pn2;
    }
}

// ---------------------------------------------------------------------------
// K2: VQ argmin. Block tile: 32 segments x 512 codes (two halves of 256).
// Half-codebook resident in smem as f32x2 pairs along D; fma.rn.f32x2 mainloop
// (packed fp32 = 2x scalar FFMA throughput on sm_100).
// smem: cb half [96][256] u64 = 196608 B  +  pooled [96][32] u64 = 24576 B.
// ---------------------------------------------------------------------------
#define K2_SMEM (96 * 256 * 8 + 96 * 32 * 8)

__global__ void __launch_bounds__(256, 1) k_argmin(const float* __restrict__ cb) {
    extern __shared__ unsigned long long sm[];
    unsigned long long* sc2 = sm;              // [96][256] column-swizzled
    unsigned long long* sp2 = sm + 96 * 256;   // [96][32]
    int tid = threadIdx.x;
    int cg  = tid & 31;   // 32 code-groups x 8 codes (c = j*32+cg)
    int sg  = tid >> 5;   // 8 seg-groups x 4 segs
    int segBase = blockIdx.x * 32;

    // stage pooled tile (transposed to d-major f32x2)
#pragma unroll
    for (int k = 0; k < 12; k++) {
        int e  = tid + k * 256;       // 0..3071
        int s  = e / 96;
        int d2 = e - s * 96;
        const float* gp = g_pooled + (size_t)(segBase + s) * DD + 2 * d2;
        unsigned long long u = ((unsigned long long)__float_as_uint(gp[1]) << 32) |
                               (unsigned long long)__float_as_uint(gp[0]);
        sp2[d2 * 32 + s] = u;
    }

    float best[4];
    int   bidx[4];
#pragma unroll
    for (int r = 0; r < 4; r++) { best[r] = 3.4e38f; bidx[r] = 0; }

    for (int half = 0; half < 2; half++) {
        __syncthreads();
        // stage codebook half: coalesced global reads, swizzled smem columns
#pragma unroll 1
        for (int it = 0; it < 48; it++) {
            int e  = tid + it * 256;   // 0..12287 float4s
            int c  = e / 48;
            int k4 = e - c * 48;
            float4 v = ((const float4*)(cb + (size_t)(half * 256 + c) * DD))[k4];
            int d2a = 2 * k4, d2b = 2 * k4 + 1;
            sc2[d2a * 256 + (c ^ (d2a & 31))] =
                ((unsigned long long)__float_as_uint(v.y) << 32) | (unsigned long long)__float_as_uint(v.x);
            sc2[d2b * 256 + (c ^ (d2b & 31))] =
                ((unsigned long long)__float_as_uint(v.w) << 32) | (unsigned long long)__float_as_uint(v.z);
        }
        __syncthreads();

        unsigned long long acc[4][8];
#pragma unroll
        for (int r = 0; r < 4; r++)
#pragma unroll
            for (int j = 0; j < 8; j++) acc[r][j] = 0ull;

        const unsigned long long* pp = sp2 + sg * 4;
#pragma unroll 2
        for (int d2 = 0; d2 < 96; d2++) {
            unsigned long long pr[4], cr[8];
            int sw = d2 & 31;
#pragma unroll
            for (int r = 0; r < 4; r++) pr[r] = pp[d2 * 32 + r];   // warp-uniform broadcast
#pragma unroll
            for (int j = 0; j < 8; j++) cr[j] = sc2[d2 * 256 + ((j * 32 + cg) ^ sw)];
#pragma unroll
            for (int r = 0; r < 4; r++)
#pragma unroll
                for (int j = 0; j < 8; j++)
                    asm("fma.rn.f32x2 %0, %1, %2, %0;"
                        : "+l"(acc[r][j]) : "l"(pr[r]), "l"(cr[j]));
        }

        // fold into running argmin:  val = ||c||^2 - 2*<p,c>
#pragma unroll
        for (int j = 0; j < 8; j++) {
            int   c  = half * 256 + j * 32 + cg;
            float cn = g_cbnorm[c];
#pragma unroll
            for (int r = 0; r < 4; r++) {
                float2 a = *(float2*)&acc[r][j];
                float val = cn - 2.f * (a.x + a.y);
                if (val < best[r] || (val == best[r] && c < bidx[r])) {
                    best[r] = val; bidx[r] = c;
                }
            }
        }
    }

    // reduce across the 32 code-group lanes of each warp
#pragma unroll
    for (int off = 16; off; off >>= 1) {
#pragma unroll
        for (int r = 0; r < 4; r++) {
            float ov = __shfl_down_sync(0xffffffffu, best[r], off);
            int   oi = __shfl_down_sync(0xffffffffu, bidx[r], off);
            if (ov < best[r] || (ov == best[r] && oi < bidx[r])) {
                best[r] = ov; bidx[r] = oi;
            }
        }
    }
    if (cg == 0) {
        float local = 0.f;
#pragma unroll
        for (int r = 0; r < 4; r++) {
            int seg = segBase + sg * 4 + r;
            g_idx[seg] = bidx[r];
            local += g_pnorm[seg] + best[r];   // = min squared distance
        }
        atomicAdd(&g_elatent, local);
    }
}

// ---------------------------------------------------------------------------
// K3: expand quantized segments to tokens (STE value = p + (c - p), matching
// reference fp32 arithmetic exactly) + idx_out broadcast.
// ---------------------------------------------------------------------------
__global__ void __launch_bounds__(64) k_scatter(const float* __restrict__ cb,
                                                float* __restrict__ q,
                                                float* __restrict__ idxo) {
    int seg = blockIdx.x;
    int t   = threadIdx.x;
    int idx = g_idx[seg];
    if (t < 48) {
        float4 c4 = ((const float4*)(cb + (size_t)idx * DD))[t];
        float4 p4 = ((const float4*)(g_pooled + (size_t)seg * DD))[t];
        float4 v;
        v.x = p4.x + (c4.x - p4.x);
        v.y = p4.y + (c4.y - p4.y);
        v.z = p4.z + (c4.z - p4.z);
        v.w = p4.w + (c4.w - p4.w);
        float4* qp = (float4*)(q + (size_t)seg * (SPAN * DD)) + t;
#pragma unroll
        for (int j = 0; j < SPAN; j++) qp[j * (DD / 4)] = v;
    } else if (t < 48 + SPAN) {
        idxo[seg * SPAN + (t - 48)] = (float)idx;
    }
}

// ---------------------------------------------------------------------------
// K4: finalize scalar loss
// ---------------------------------------------------------------------------
__global__ void k_final(float* __restrict__ loss_out) {
    float e  = g_elatent * (1.0f / ((float)NSEG * (float)DD));
    float br = (float)g_bcount * (1.0f / (float)NTOK);
    float bl = br - (1.0f / SPAN);
    loss_out[0] = 0.25f * e + 0.01f * bl * bl;
}

// ---------------------------------------------------------------------------
extern "C" void kernel_launch(void* const* d_in, const int* in_sizes, int n_in,
                              void* d_out, int out_size) {
    const float* x  = (const float*)d_in[0];
    const float* cb = (const float*)d_in[1];
    const float* w  = (const float*)d_in[2];
    const float* bb = (const float*)d_in[3];
    float* out  = (float*)d_out;
    float* q    = out;
    float* loss = out + OFF_LOSS;
    float* idxo = out + OFF_IDX;
    float* bnd  = out + OFF_BND;

    cudaFuncSetAttribute(k_argmin, cudaFuncAttributeMaxDynamicSharedMemorySize, K2_SMEM);

    k_init<<<2, 256>>>(cb);
    k_pool<<<NSEG, 192>>>(x, w, bb, bnd);
    k_argmin<<<NSEG / 32, 256, K2_SMEM>>>(cb);
    k_scatter<<<NSEG, 64>>>(cb, q, idxo);
    k_final<<<1, 1>>>(loss);
}

// round 2
// speedup vs baseline: 1.4574x; 1.4574x over previous
#include <cuda_runtime.h>
#include <cstdint>
#include <cstddef>

// Problem constants
#define BB    16
#define TT    8192
#define DD    192
#define KC    512
#define SPAN  8
#define NSEG  16384
#define NTOK  131072

// Output packing: q_out [B,T,D] f32 | total_loss [1] | idx_out [B,T] | boundaries [B,T]
#define OFF_LOSS 25165824
#define OFF_IDX  25165825
#define OFF_BND  25296897

// k_argmin tiling
#define TILE_M   128               // segments per block
#define CHUNK    64                // codes per pipeline chunk
#define NCHUNK   (KC / CHUNK)      // 8
#define ND4      (DD / 4)          // 48 float4 groups along D
#define SM_POOL_F4 (ND4 * TILE_M)  // 6144 float4
#define SM_CB_F4   (ND4 * CHUNK)   // 3072 float4
#define POOL_BYTES (SM_POOL_F4 * 16)
#define CB_BYTES   (SM_CB_F4 * 16)
#define K2_SMEM   ((SM_POOL_F4 + 2 * SM_CB_F4) * 16)   // 196608 B

// Device scratch (no allocations allowed)
__device__ float  g_pooled[NSEG * DD];                      // [seg][d]
__device__ float4 g_pT[(NSEG / TILE_M) * ND4 * TILE_M];     // [tile][d4][s^(d4&31)]
__device__ float4 g_cbimg[NCHUNK * ND4 * CHUNK];            // [chunk][d4][c&63]
__device__ float  g_pnorm[NSEG];
__device__ int    g_idx[NSEG];
__device__ float  g_cbnorm[KC];
__device__ float  g_elatent;
__device__ int    g_bcount;

// ---------------------------------------------------------------------------
// PTX helpers
// ---------------------------------------------------------------------------
__device__ __forceinline__ unsigned smaddr(const void* p) {
    return (unsigned)__cvta_generic_to_shared(p);
}
__device__ __forceinline__ void mbar_init(unsigned a, unsigned cnt) {
    asm volatile("mbarrier.init.shared.b64 [%0], %1;" :: "r"(a), "r"(cnt) : "memory");
}
__device__ __forceinline__ void mbar_expect(unsigned a, unsigned bytes) {
    asm volatile("mbarrier.arrive.expect_tx.shared.b64 _, [%0], %1;" :: "r"(a), "r"(bytes) : "memory");
}
__device__ __forceinline__ void mbar_arrive(unsigned a) {
    asm volatile("mbarrier.arrive.shared.b64 _, [%0];" :: "r"(a) : "memory");
}
__device__ __forceinline__ void mbar_wait(unsigned a, unsigned par) {
    asm volatile(
        "{\n\t.reg .pred P;\n"
        "WL%=:\n\t"
        "mbarrier.try_wait.parity.acquire.cta.shared::cta.b64 P, [%0], %1;\n\t"
        "@!P bra WL%=;\n\t}"
        :: "r"(a), "r"(par) : "memory");
}
__device__ __forceinline__ void bulk_g2s(unsigned dst, const void* src, unsigned bytes, unsigned mbar) {
    asm volatile(
        "cp.async.bulk.shared::cluster.global.mbarrier::complete_tx::bytes [%0], [%1], %2, [%3];"
        :: "r"(dst), "l"(src), "r"(bytes), "r"(mbar) : "memory");
}
__device__ __forceinline__ void ffma2(unsigned long long& a, unsigned long long x, unsigned long long y) {
    asm("fma.rn.f32x2 %0, %1, %2, %0;" : "+l"(a) : "l"(x), "l"(y));
}

// ---------------------------------------------------------------------------
// K0: reset accumulators + codebook squared norms
// ---------------------------------------------------------------------------
__global__ void k_init(const float* __restrict__ cb) {
    int c = blockIdx.x * 256 + threadIdx.x;
    if (c == 0) { g_elatent = 0.f; g_bcount = 0; }
    if (c < KC) {
        const float4* r = (const float4*)(cb + (size_t)c * DD);
        float s = 0.f;
#pragma unroll
        for (int k = 0; k < ND4; k++) {
            float4 v = r[k];
            s += v.x * v.x + v.y * v.y + v.z * v.z + v.w * v.w;
        }
        g_cbnorm[c] = s;
    }
}

// ---------------------------------------------------------------------------
// K0b: build d4-major codebook image for bulk staging (swizzle-free layout)
// ---------------------------------------------------------------------------
__global__ void __launch_bounds__(ND4) k_prep(const float* __restrict__ cb) {
    int c = blockIdx.x, d4 = threadIdx.x;
    float4 v = ((const float4*)(cb + (size_t)c * DD))[d4];
    g_cbimg[((size_t)(c >> 6) * ND4 + d4) * CHUNK + (c & (CHUNK - 1))] = v;
}

// ---------------------------------------------------------------------------
// K1: segment pooling + pooled-norm + boundary predictor + transposed image
// ---------------------------------------------------------------------------
__global__ void __launch_bounds__(192) k_pool(const float* __restrict__ x,
                                              const float* __restrict__ w,
                                              const float* __restrict__ bbias,
                                              float* __restrict__ out_bnd) {
    int seg = blockIdx.x;
    int d   = threadIdx.x;
    const float* xp = x + (size_t)seg * (SPAN * DD) + d;
    float wd  = w[d];
    float part[SPAN];
    float sum = 0.f;
#pragma unroll
    for (int j = 0; j < SPAN; j++) {
        float v = xp[(size_t)j * DD];
        sum += v;
        part[j] = v * wd;
    }
    float p = sum * (1.0f / SPAN);
    g_pooled[(size_t)seg * DD + d] = p;

    // transposed, swizzled image for k_argmin bulk staging
    float p1 = __shfl_down_sync(0xffffffffu, p, 1);
    float p2 = __shfl_down_sync(0xffffffffu, p, 2);
    float p3 = __shfl_down_sync(0xffffffffu, p, 3);
    if ((d & 3) == 0) {
        int d4 = d >> 2, s = seg & (TILE_M - 1);
        g_pT[((size_t)(seg >> 7) * ND4 + d4) * TILE_M + (s ^ (d4 & 31))] =
            make_float4(p, p1, p2, p3);
    }

    float pn = p * p;
#pragma unroll
    for (int off = 16; off; off >>= 1) {
#pragma unroll
        for (int j = 0; j < SPAN; j++)
            part[j] += __shfl_down_sync(0xffffffffu, part[j], off);
        pn += __shfl_down_sync(0xffffffffu, pn, off);
    }
    __shared__ float sh[6][9];
    int wp = d >> 5, ln = d & 31;
    if (ln == 0) {
#pragma unroll
        for (int j = 0; j < SPAN; j++) sh[wp][j] = part[j];
        sh[wp][8] = pn;
    }
    __syncthreads();
    if (d < SPAN) {
        float z = bbias[0];
#pragma unroll
        for (int k = 0; k < 6; k++) z += sh[k][d];
        bool hi = z > 0.f;
        out_bnd[seg * SPAN + d] = hi ? 1.f : 0.f;
        unsigned bal = __ballot_sync(0x000000ffu, hi);
        if (d == 0) atomicAdd(&g_bcount, __popc(bal & 0xffu));
    } else if (d == SPAN) {
        float pn2 = 0.f;
#pragma unroll
        for (int k = 0; k < 6; k++) pn2 += sh[k][8];
        g_pnorm[seg] = pn2;
    }
}

// ---------------------------------------------------------------------------
// K2: VQ argmin. Tile: 128 segments x 512 codes. Pooled tile resident (98KB),
// codebook streamed in 64-code chunks (48KB x2, double buffered, cp.async.bulk
// pipelined against the fma.rn.f32x2 mainloop).
// Per thread: 16 segments x 2 codes. FMA2-bound by design.
// ---------------------------------------------------------------------------
__global__ void __launch_bounds__(256, 1) k_argmin() {
    extern __shared__ float4 s4[];
    float4* sp4 = s4;                         // pooled [48][128]
    float4* sc4 = s4 + SM_POOL_F4;            // cb chunk buffers [2][48][64]
    __shared__ __align__(8) unsigned long long mb[5];  // pool_full, full0, full1, empty0, empty1

    int tid = threadIdx.x;
    int cg  = tid & 31;     // lane -> code within group of 32
    int sg  = tid >> 5;     // warp -> 16-segment group
    int tile = blockIdx.x;

    unsigned mPool  = smaddr(&mb[0]);
    unsigned mFull0 = smaddr(&mb[1]);
    unsigned mFull1 = smaddr(&mb[2]);
    unsigned mEmp0  = smaddr(&mb[3]);
    unsigned mEmp1  = smaddr(&mb[4]);

    if (tid == 0) {
        mbar_init(mPool, 1);
        mbar_init(mFull0, 1);
        mbar_init(mFull1, 1);
        mbar_init(mEmp0, 256);
        mbar_init(mEmp1, 256);
    }
    __syncthreads();

    if (tid == 0) {
        mbar_expect(mPool, POOL_BYTES);
        bulk_g2s(smaddr(sp4), &g_pT[(size_t)tile * SM_POOL_F4], POOL_BYTES, mPool);
        mbar_expect(mFull0, CB_BYTES);
        bulk_g2s(smaddr(sc4), &g_cbimg[0], CB_BYTES, mFull0);
        mbar_expect(mFull1, CB_BYTES);
        bulk_g2s(smaddr(sc4 + SM_CB_F4), &g_cbimg[SM_CB_F4], CB_BYTES, mFull1);
    }
    mbar_wait(mPool, 0);

    float best[16];
    int   bidx[16];
#pragma unroll
    for (int r = 0; r < 16; r++) { best[r] = 3.4e38f; bidx[r] = 0; }

    const ulonglong2* pp2 = (const ulonglong2*)sp4;

    for (int ch = 0; ch < NCHUNK; ch++) {
        int b = ch & 1;
        unsigned par = (ch >> 1) & 1;
        mbar_wait(b ? mFull1 : mFull0, par);

        unsigned long long acc0[16], acc1[16];
#pragma unroll
        for (int r = 0; r < 16; r++) { acc0[r] = 0ull; acc1[r] = 0ull; }

        const ulonglong2* cb2 = (const ulonglong2*)(sc4 + b * SM_CB_F4);
#pragma unroll 4
        for (int d4 = 0; d4 < ND4; d4++) {
            ulonglong2 c0 = cb2[d4 * CHUNK + cg];
            ulonglong2 c1 = cb2[d4 * CHUNK + 32 + cg];
            int sw = d4 & 31;
            int pb = d4 * TILE_M;
            int sb = sg * 16;
#pragma unroll
            for (int r = 0; r < 16; r++) {
                ulonglong2 pv = pp2[pb + ((sb + r) ^ sw)];
                ffma2(acc0[r], pv.x, c0.x);
                ffma2(acc0[r], pv.y, c0.y);
                ffma2(acc1[r], pv.x, c1.x);
                ffma2(acc1[r], pv.y, c1.y);
            }
        }

        // fold this chunk's 2 codes per lane into the running argmin
#pragma unroll
        for (int j = 0; j < 2; j++) {
            int c = ch * CHUNK + j * 32 + cg;
            float cn = __ldg(&g_cbnorm[c]);
#pragma unroll
            for (int r = 0; r < 16; r++) {
                unsigned long long a = j ? acc1[r] : acc0[r];
                float lo = __uint_as_float((unsigned)a);
                float hi = __uint_as_float((unsigned)(a >> 32));
                float val = cn - 2.f * (lo + hi);
                if (val < best[r] || (val == best[r] && c < bidx[r])) {
                    best[r] = val; bidx[r] = c;
                }
            }
        }

        mbar_arrive(b ? mEmp1 : mEmp0);
        if (tid == 0 && ch + 2 < NCHUNK) {
            mbar_wait(b ? mEmp1 : mEmp0, par);
            mbar_expect(b ? mFull1 : mFull0, CB_BYTES);
            bulk_g2s(smaddr(sc4 + b * SM_CB_F4),
                     &g_cbimg[(size_t)(ch + 2) * SM_CB_F4], CB_BYTES,
                     b ? mFull1 : mFull0);
        }
    }

    // reduce across the 32 code lanes of each warp
#pragma unroll
    for (int off = 16; off; off >>= 1) {
#pragma unroll
        for (int r = 0; r < 16; r++) {
            float ov = __shfl_down_sync(0xffffffffu, best[r], off);
            int   oi = __shfl_down_sync(0xffffffffu, bidx[r], off);
            if (ov < best[r] || (ov == best[r] && oi < bidx[r])) {
                best[r] = ov; bidx[r] = oi;
            }
        }
    }
    if (cg == 0) {
        float local = 0.f;
#pragma unroll
        for (int r = 0; r < 16; r++) {
            int seg = tile * TILE_M + sg * 16 + r;
            g_idx[seg] = bidx[r];
            local += g_pnorm[seg] + best[r];
        }
        atomicAdd(&g_elatent, local);
    }
}

// ---------------------------------------------------------------------------
// K3: expand quantized segments to tokens (STE value = p + (c - p)) + idx_out
// 4 segments per 256-thread block.
// ---------------------------------------------------------------------------
__global__ void __launch_bounds__(256) k_scatter(const float* __restrict__ cb,
                                                 float* __restrict__ q,
                                                 float* __restrict__ idxo) {
    int tid = threadIdx.x;
    int seg = blockIdx.x * 4 + (tid >> 6);
    int t   = tid & 63;
    int idx = g_idx[seg];
    if (t < 48) {
        float4 c4 = ((const float4*)(cb + (size_t)idx * DD))[t];
        float4 p4 = ((const float4*)(g_pooled + (size_t)seg * DD))[t];
        float4 v;
        v.x = p4.x + (c4.x - p4.x);
        v.y = p4.y + (c4.y - p4.y);
        v.z = p4.z + (c4.z - p4.z);
        v.w = p4.w + (c4.w - p4.w);
        float4* qp = (float4*)(q + (size_t)seg * (SPAN * DD)) + t;
#pragma unroll
        for (int j = 0; j < SPAN; j++) qp[j * (DD / 4)] = v;
    } else if (t < 48 + SPAN) {
        idxo[seg * SPAN + (t - 48)] = (float)idx;
    }
}

// ---------------------------------------------------------------------------
// K4: finalize scalar loss
// ---------------------------------------------------------------------------
__global__ void k_final(float* __restrict__ loss_out) {
    float e  = g_elatent * (1.0f / ((float)NSEG * (float)DD));
    float br = (float)g_bcount * (1.0f / (float)NTOK);
    float bl = br - (1.0f / SPAN);
    loss_out[0] = 0.25f * e + 0.01f * bl * bl;
}

// ---------------------------------------------------------------------------
extern "C" void kernel_launch(void* const* d_in, const int* in_sizes, int n_in,
                              void* d_out, int out_size) {
    const float* x  = (const float*)d_in[0];
    const float* cb = (const float*)d_in[1];
    const float* w  = (const float*)d_in[2];
    const float* bb = (const float*)d_in[3];
    float* out  = (float*)d_out;
    float* q    = out;
    float* loss = out + OFF_LOSS;
    float* idxo = out + OFF_IDX;
    float* bnd  = out + OFF_BND;

    cudaFuncSetAttribute(k_argmin, cudaFuncAttributeMaxDynamicSharedMemorySize, K2_SMEM);

    k_init<<<2, 256>>>(cb);
    k_prep<<<KC, ND4>>>(cb);
    k_pool<<<NSEG, 192>>>(x, w, bb, bnd);
    k_argmin<<<NSEG / TILE_M, 256, K2_SMEM>>>();
    k_scatter<<<NSEG / 4, 256>>>(cb, q, idxo);
    k_final<<<1, 1>>>(loss);
}